// round 9
// baseline (speedup 1.0000x reference)
#include <cuda_runtime.h>

// CWT: out[b,i,n] = Re{ sum_{k=0}^{4} w[k] * signal[b, n - wl_i + k] }
// w[k] = exp(-0.5 k^2) * exp(j*2pi*k/6), nrm=1. |w[5]|~1.9e-6, |w[6]|~1.5e-8:
// K=5 keeps rel_err ~2e-6 vs the 1e-3 threshold.
// Output buffer = float32 real part (out_size == 524288, confirmed R5-R8).
// V=2 outputs/thread -> window of 6 samples = exactly 3 aligned float2 loads
// (wl and n0 both even -> base even). Grid (8,32,4) x 256 = 1024 CTAs, 1 wave.

#define CWT_NSCALES 32
#define CWT_L       4096
#define CWT_B       4
#define CWT_K       5
#define CWT_V       2
#define CWT_TPB     256

__constant__ int c_wl[CWT_NSCALES] = {
      64,  194,  324,  454,  584,  714,  844,  974,
    1104, 1234, 1364, 1494, 1624, 1754, 1884, 2014,
    2048, 2048, 2048, 2048, 2048, 2048, 2048, 2048,
    2048, 2048, 2048, 2048, 2048, 2048, 2048, 2048
};

// w_re[k] = exp(-0.5 k^2) * cos(2 pi k / 6)
__device__ __constant__ float c_wr[CWT_K] = {
    1.0f,                   0.3032653298563167f,   -0.06766764161830635f,
   -0.011108996538242306f, -1.6773131395125593e-4f
};
// w_im[k] (fallback interleaved mode only)
__device__ __constant__ float c_wi[CWT_K] = {
    0.0f,                   0.5252752119703823f,     0.11720384084196092f,
    0.0f,                  -2.9051333293715680e-4f
};

template <int MODE>  // 0: real-only floats; 1: interleaved re/im floats
__global__ void __launch_bounds__(CWT_TPB)
cwt81003_kernel(const float* __restrict__ sig, float* __restrict__ out)
{
    const int i  = blockIdx.y;                       // scale
    const int b  = blockIdx.z;                       // batch
    const int n0 = (blockIdx.x * CWT_TPB + threadIdx.x) * CWT_V;  // even

    const int wl   = c_wl[i];
    const int base = n0 - wl;                        // even

    float r0 = 0.0f, r1 = 0.0f;
    float i0 = 0.0f, i1 = 0.0f;

    if (n0 + CWT_V + CWT_K - 2 >= wl) {              // window touches signal
        float x[CWT_V + CWT_K - 1];                  // 6 samples
        const float* p = sig + b * CWT_L + base;
        if (base >= 0) {
            const float2* p2 = (const float2*)p;     // 8B-aligned
            float2 a = __ldg(p2 + 0);
            float2 c = __ldg(p2 + 1);
            float2 d = __ldg(p2 + 2);
            x[0] = a.x; x[1] = a.y; x[2] = c.x;
            x[3] = c.y; x[4] = d.x; x[5] = d.y;
        } else {
            #pragma unroll
            for (int j = 0; j < CWT_V + CWT_K - 1; j++)
                x[j] = (base + j >= 0) ? __ldg(p + j) : 0.0f;
        }
        #pragma unroll
        for (int k = 0; k < CWT_K; k++) {
            r0 = fmaf(c_wr[k], x[k],     r0);
            r1 = fmaf(c_wr[k], x[k + 1], r1);
            if (MODE == 1) {
                i0 = fmaf(c_wi[k], x[k],     i0);
                i1 = fmaf(c_wi[k], x[k + 1], i1);
            }
        }
    }

    const long row = (long)(b * CWT_NSCALES + i);
    if (MODE == 0) {
        *(float2*)(out + row * CWT_L + n0) = make_float2(r0, r1);
    } else {
        *(float4*)(out + 2 * (row * CWT_L + n0)) = make_float4(r0, i0, r1, i1);
    }
}

extern "C" void kernel_launch(void* const* d_in, const int* in_sizes, int n_in,
                              void* d_out, int out_size)
{
    const float* sig = (const float*)d_in[0];
    float* out = (float*)d_out;

    const long logical = (long)CWT_B * CWT_NSCALES * CWT_L;  // 524288 outputs
    dim3 grid(CWT_L / (CWT_V * CWT_TPB), CWT_NSCALES, CWT_B); // (8, 32, 4)

    if ((long)out_size >= 2 * logical)
        cwt81003_kernel<1><<<grid, CWT_TPB>>>(sig, out);
    else
        cwt81003_kernel<0><<<grid, CWT_TPB>>>(sig, out);
}

// round 10
// speedup vs baseline: 3.0918x; 3.0918x over previous
#include <cuda_runtime.h>

// CWT: out[b,i,n] = Re{ sum_{k=0}^{4} w[k] * signal[b, n - wl_i + k] }
// w[k] = exp(-0.5 k^2) * exp(j*2pi*k/6), nrm=1. |w[5]|~1.9e-6 -> K=5 gives
// rel_err ~1.8e-6 (measured R9) vs threshold 1e-3.
// Output buffer = float32 real part (out_size == 524288, confirmed R5-R9).
// Best-measured shape (R8): flat 1D grid, 1024 CTAs x 256 threads, V=2.
// 6-sample window = exactly 3 aligned float2 loads (wl, n0 even -> base even).

#define CWT_NSCALES 32
#define CWT_L       4096
#define CWT_B       4
#define CWT_K       5
#define CWT_V       2
#define CWT_TPB     256

__constant__ int c_wl[CWT_NSCALES] = {
      64,  194,  324,  454,  584,  714,  844,  974,
    1104, 1234, 1364, 1494, 1624, 1754, 1884, 2014,
    2048, 2048, 2048, 2048, 2048, 2048, 2048, 2048,
    2048, 2048, 2048, 2048, 2048, 2048, 2048, 2048
};

// w_re[k] = exp(-0.5 k^2) * cos(2 pi k / 6)
__device__ __constant__ float c_wr[CWT_K] = {
    1.0f,                   0.3032653298563167f,   -0.06766764161830635f,
   -0.011108996538242306f, -1.6773131395125593e-4f
};
// w_im[k] (fallback interleaved mode only)
__device__ __constant__ float c_wi[CWT_K] = {
    0.0f,                   0.5252752119703823f,     0.11720384084196092f,
    0.0f,                  -2.9051333293715680e-4f
};

template <int MODE>  // 0: real-only floats; 1: interleaved re/im floats
__global__ void __launch_bounds__(CWT_TPB)
cwt81003_kernel(const float* __restrict__ sig, float* __restrict__ out)
{
    const int t   = blockIdx.x * CWT_TPB + threadIdx.x;  // 0 .. 262143
    const int row = t >> 11;                  // (b*32+i); 2048 threads per row
    const int n0  = (t & 2047) * CWT_V;       // even
    const int i   = row & (CWT_NSCALES - 1);
    const int b   = row >> 5;

    const int wl   = c_wl[i];
    const int base = n0 - wl;                 // even

    float r0 = 0.0f, r1 = 0.0f;
    float i0 = 0.0f, i1 = 0.0f;

    if (n0 + CWT_V + CWT_K - 2 >= wl) {       // window touches the signal
        float x[CWT_V + CWT_K - 1];           // 6 samples
        const float* p = sig + b * CWT_L + base;
        if (base >= 0) {
            const float2* p2 = (const float2*)p;  // 8B-aligned
            float2 a = __ldg(p2 + 0);
            float2 c = __ldg(p2 + 1);
            float2 d = __ldg(p2 + 2);
            x[0] = a.x; x[1] = a.y; x[2] = c.x;
            x[3] = c.y; x[4] = d.x; x[5] = d.y;
        } else {
            #pragma unroll
            for (int j = 0; j < CWT_V + CWT_K - 1; j++)
                x[j] = (base + j >= 0) ? __ldg(p + j) : 0.0f;
        }
        #pragma unroll
        for (int k = 0; k < CWT_K; k++) {
            r0 = fmaf(c_wr[k], x[k],     r0);
            r1 = fmaf(c_wr[k], x[k + 1], r1);
            if (MODE == 1) {
                i0 = fmaf(c_wi[k], x[k],     i0);
                i1 = fmaf(c_wi[k], x[k + 1], i1);
            }
        }
    }

    if (MODE == 0) {
        *(float2*)(out + (long)row * CWT_L + n0) = make_float2(r0, r1);
    } else {
        *(float4*)(out + 2 * ((long)row * CWT_L + n0)) = make_float4(r0, i0, r1, i1);
    }
}

extern "C" void kernel_launch(void* const* d_in, const int* in_sizes, int n_in,
                              void* d_out, int out_size)
{
    const float* sig = (const float*)d_in[0];
    float* out = (float*)d_out;

    const long logical = (long)CWT_B * CWT_NSCALES * CWT_L;   // 524288 outputs
    const int nblocks  = (int)(logical / CWT_V / CWT_TPB);    // 1024

    if ((long)out_size >= 2 * logical)
        cwt81003_kernel<1><<<nblocks, CWT_TPB>>>(sig, out);
    else
        cwt81003_kernel<0><<<nblocks, CWT_TPB>>>(sig, out);
}